// round 1
// baseline (speedup 1.0000x reference)
#include <cuda_runtime.h>

// Problem constants
#define BB 4
#define TT 2048
#define DD 1024
#define HH 16
#define HD 64
// Derived
#define BT (BB * TT)        // 8192
#define BHT (BB * HH * TT)  // 131072

// Scratch (allocation-free rule: __device__ globals)
__device__ float g_Q[BB * HH * TT * HD];   // [B,H,T,HD]
__device__ float g_K[BB * HH * TT * HD];
__device__ float g_V[BB * HH * TT * HD];
__device__ float g_Y[BB * TT * DD];        // [B,T,D] attention output

// ---------------------------------------------------------------------------
// Tiled FP32 GEMM core: C_tile(64x64) = A[M,K] @ B[K,N] for block (bm, bn).
// 256 threads, BK=16, each thread computes a 4x4 micro-tile.
// ---------------------------------------------------------------------------
__device__ __forceinline__ void gemm_compute(const float* __restrict__ A,
                                             const float* __restrict__ Bm,
                                             int K, int N, int bm, int bn,
                                             float acc[4][4])
{
    __shared__ float As[16][64];   // transposed: As[k][m]
    __shared__ float Bs[16][64];   // Bs[k][n]
    const int tid  = threadIdx.x;
    const int tx   = tid & 15;          // 0..15 (n direction)
    const int ty   = tid >> 4;          // 0..15 (m direction)
    const int arow = tid >> 2;          // 0..63
    const int acol = (tid & 3) << 2;    // 0,4,8,12
    const int brow = tid >> 4;          // 0..15
    const int bcol = (tid & 15) << 2;   // 0..60

    for (int k0 = 0; k0 < K; k0 += 16) {
        float4 av = *(const float4*)&A[(bm + arow) * K + k0 + acol];
        As[acol + 0][arow] = av.x;
        As[acol + 1][arow] = av.y;
        As[acol + 2][arow] = av.z;
        As[acol + 3][arow] = av.w;
        *(float4*)&Bs[brow][bcol] =
            *(const float4*)&Bm[(k0 + brow) * N + bn + bcol];
        __syncthreads();
        #pragma unroll
        for (int kk = 0; kk < 16; kk++) {
            float4 a4 = *(const float4*)&As[kk][ty * 4];
            float4 b4 = *(const float4*)&Bs[kk][tx * 4];
            float a[4] = {a4.x, a4.y, a4.z, a4.w};
            float b[4] = {b4.x, b4.y, b4.z, b4.w};
            #pragma unroll
            for (int i = 0; i < 4; i++)
                #pragma unroll
                for (int j = 0; j < 4; j++)
                    acc[i][j] = fmaf(a[i], b[j], acc[i][j]);
        }
        __syncthreads();
    }
}

// ---------------------------------------------------------------------------
// Kernel 1: QKV projection.  qkv = x @ w_qkv + b_qkv, scattered to
// g_Q/g_K/g_V in [B,H,T,HD] layout. N-tile (64 wide) always lies inside one
// (which, head) block since 64 | 1024 boundaries.
// ---------------------------------------------------------------------------
__global__ __launch_bounds__(256)
void qkv_gemm_kernel(const float* __restrict__ x,
                     const float* __restrict__ w,
                     const float* __restrict__ bias)
{
    float acc[4][4] = {};
    const int bm = blockIdx.y * 64;
    const int bn = blockIdx.x * 64;
    gemm_compute(x, w, DD, 3 * DD, bm, bn, acc);

    const int tx = threadIdx.x & 15;
    const int ty = threadIdx.x >> 4;
    const int which = bn >> 10;              // 0=q,1=k,2=v
    const int h     = (bn & 1023) >> 6;      // head
    float* dst = (which == 0) ? g_Q : (which == 1) ? g_K : g_V;
    float4 bv = *(const float4*)&bias[bn + tx * 4];
    #pragma unroll
    for (int i = 0; i < 4; i++) {
        int m = bm + ty * 4 + i;             // 0..8191 (= b*T + t)
        int b = m >> 11, t = m & 2047;
        float4 v;
        v.x = acc[i][0] + bv.x;
        v.y = acc[i][1] + bv.y;
        v.z = acc[i][2] + bv.z;
        v.w = acc[i][3] + bv.w;
        *(float4*)&dst[(((b << 4) + h) * TT + t) * HD + tx * 4] = v;
    }
}

// ---------------------------------------------------------------------------
// Kernel 2: causal flash attention, fp32.
// Grid: (T/64, B*H). 64 threads/CTA; thread r owns query row m = qblk*64 + r:
// q[64] and o[64] live in registers; K/V tiles (64x64) staged in smem;
// online softmax over 16-key chunks.
// ---------------------------------------------------------------------------
__global__ __launch_bounds__(64)
void attn_kernel()
{
    const int bh   = blockIdx.y;           // b*H + h
    const int b    = bh >> 4;
    const int h    = bh & 15;
    const int qblk = blockIdx.x;           // 0..31
    const int r    = threadIdx.x;          // 0..63
    const int m    = qblk * 64 + r;

    __shared__ float Ks[64 * 64];
    __shared__ float Vs[64 * 64];

    float q[64], o[64];
    const float* qrow = g_Q + (bh * TT + m) * HD;
    #pragma unroll
    for (int d4 = 0; d4 < 16; d4++) {
        float4 v = ((const float4*)qrow)[d4];
        q[d4 * 4 + 0] = v.x; q[d4 * 4 + 1] = v.y;
        q[d4 * 4 + 2] = v.z; q[d4 * 4 + 3] = v.w;
    }
    #pragma unroll
    for (int d = 0; d < 64; d++) o[d] = 0.f;

    float mi = -1e30f, li = 0.f;
    const float scale = 0.125f;            // 1/sqrt(64)

    #pragma unroll 1
    for (int jb = 0; jb <= qblk; jb++) {
        const float* kt = g_K + (bh * TT + jb * 64) * HD;
        const float* vt = g_V + (bh * TT + jb * 64) * HD;
        #pragma unroll
        for (int l = 0; l < 16; l++) {     // 1024 float4 / 64 threads
            ((float4*)Ks)[r + l * 64] = ((const float4*)kt)[r + l * 64];
            ((float4*)Vs)[r + l * 64] = ((const float4*)vt)[r + l * 64];
        }
        __syncthreads();

        const int kbase = jb * 64;
        #pragma unroll
        for (int c = 0; c < 4; c++) {      // 16-key chunks
            float s[16];
            #pragma unroll
            for (int kk = 0; kk < 16; kk++) {
                const int key = c * 16 + kk;
                float dot = 0.f;
                const float4* krow = (const float4*)(Ks + key * 64);
                #pragma unroll
                for (int d4 = 0; d4 < 16; d4++) {
                    float4 kv = krow[d4];
                    dot = fmaf(q[d4 * 4 + 0], kv.x, dot);
                    dot = fmaf(q[d4 * 4 + 1], kv.y, dot);
                    dot = fmaf(q[d4 * 4 + 2], kv.z, dot);
                    dot = fmaf(q[d4 * 4 + 3], kv.w, dot);
                }
                s[kk] = (kbase + key <= m) ? dot * scale : -1e30f;
            }
            float mnew = mi;
            #pragma unroll
            for (int kk = 0; kk < 16; kk++) mnew = fmaxf(mnew, s[kk]);
            const float alpha = __expf(mi - mnew);
            float ps = 0.f;
            #pragma unroll
            for (int kk = 0; kk < 16; kk++) {
                s[kk] = __expf(s[kk] - mnew);
                ps += s[kk];
            }
            li = li * alpha + ps;
            mi = mnew;
            #pragma unroll
            for (int d = 0; d < 64; d++) o[d] *= alpha;
            #pragma unroll
            for (int kk = 0; kk < 16; kk++) {
                const float p = s[kk];
                const float4* vrow = (const float4*)(Vs + (c * 16 + kk) * 64);
                #pragma unroll
                for (int d4 = 0; d4 < 16; d4++) {
                    float4 vv = vrow[d4];
                    o[d4 * 4 + 0] = fmaf(p, vv.x, o[d4 * 4 + 0]);
                    o[d4 * 4 + 1] = fmaf(p, vv.y, o[d4 * 4 + 1]);
                    o[d4 * 4 + 2] = fmaf(p, vv.z, o[d4 * 4 + 2]);
                    o[d4 * 4 + 3] = fmaf(p, vv.w, o[d4 * 4 + 3]);
                }
            }
        }
        __syncthreads();
    }

    const float inv = 1.f / li;
    float* yrow = g_Y + (b * TT + m) * DD + h * HD;
    #pragma unroll
    for (int d4 = 0; d4 < 16; d4++) {
        float4 v;
        v.x = o[d4 * 4 + 0] * inv;
        v.y = o[d4 * 4 + 1] * inv;
        v.z = o[d4 * 4 + 2] * inv;
        v.w = o[d4 * 4 + 3] * inv;
        ((float4*)yrow)[d4] = v;
    }
}

// ---------------------------------------------------------------------------
// Kernel 3: output projection.  out = g_Y @ w_out + b_out
// ---------------------------------------------------------------------------
__global__ __launch_bounds__(256)
void proj_gemm_kernel(const float* __restrict__ w,
                      const float* __restrict__ bias,
                      float* __restrict__ out)
{
    float acc[4][4] = {};
    const int bm = blockIdx.y * 64;
    const int bn = blockIdx.x * 64;
    gemm_compute(g_Y, w, DD, DD, bm, bn, acc);

    const int tx = threadIdx.x & 15;
    const int ty = threadIdx.x >> 4;
    float4 bv = *(const float4*)&bias[bn + tx * 4];
    #pragma unroll
    for (int i = 0; i < 4; i++) {
        int mrow = bm + ty * 4 + i;
        float4 v;
        v.x = acc[i][0] + bv.x;
        v.y = acc[i][1] + bv.y;
        v.z = acc[i][2] + bv.z;
        v.w = acc[i][3] + bv.w;
        *(float4*)&out[mrow * DD + bn + tx * 4] = v;
    }
}

// ---------------------------------------------------------------------------
// Launch. Inputs (metadata order): x, causal_mask(unused), w_qkv, b_qkv,
// w_out, b_out. Output: [B,T,D] fp32.
// ---------------------------------------------------------------------------
extern "C" void kernel_launch(void* const* d_in, const int* in_sizes, int n_in,
                              void* d_out, int out_size)
{
    const float* x     = (const float*)d_in[0];
    const float* w_qkv = (const float*)d_in[2];
    const float* b_qkv = (const float*)d_in[3];
    const float* w_out = (const float*)d_in[4];
    const float* b_out = (const float*)d_in[5];
    float* out = (float*)d_out;

    qkv_gemm_kernel<<<dim3((3 * DD) / 64, BT / 64), 256>>>(x, w_qkv, b_qkv);
    attn_kernel<<<dim3(TT / 64, BB * HH), 64>>>();
    proj_gemm_kernel<<<dim3(DD / 64, BT / 64), 256>>>(w_out, b_out, out);
}

// round 2
// speedup vs baseline: 1.3673x; 1.3673x over previous
#include <cuda_runtime.h>
#include <cstdint>

// Problem constants
#define BB 4
#define TT 2048
#define DD 1024
#define HH 16
#define HD 64
#define BT (BB * TT)        // 8192

// Scratch (allocation-free rule: __device__ globals)
__device__ float g_Q[BB * HH * TT * HD];   // [B,H,T,HD]
__device__ float g_K[BB * HH * TT * HD];
__device__ float g_V[BB * HH * TT * HD];
__device__ float g_Y[BB * TT * DD];        // [B,T,D] attention output

__device__ __forceinline__ uint32_t f2tf(float f) {
    uint32_t u;
    asm("cvt.rna.tf32.f32 %0, %1;" : "=r"(u) : "f"(f));
    return u;
}

__device__ __forceinline__ void mma_tf32(float c[4], const uint32_t a[4],
                                         const uint32_t b[2]) {
    asm volatile(
        "mma.sync.aligned.m16n8k8.row.col.f32.tf32.tf32.f32 "
        "{%0,%1,%2,%3}, {%4,%5,%6,%7}, {%8,%9}, {%0,%1,%2,%3};"
        : "+f"(c[0]), "+f"(c[1]), "+f"(c[2]), "+f"(c[3])
        : "r"(a[0]), "r"(a[1]), "r"(a[2]), "r"(a[3]), "r"(b[0]), "r"(b[1]));
}

// ---------------------------------------------------------------------------
// tf32 tensor-core GEMM: C[M,N] = A[M,K] @ B[K,N] + bias.
// CTA tile 128x128, BK=16, 256 threads = 8 warps (4 M x 2 N), warp tile 32x64.
// Double-buffered smem. EPI=0: scatter to g_Q/g_K/g_V ([B,H,T,HD]).
// EPI=1: dense write to Cout [M,N].
// ---------------------------------------------------------------------------
#define ASTR 20    // A smem row stride (floats): [m][k], conflict-free frags
#define BSTR 132   // B smem row stride (floats): [k][n], conflict-free frags

template <int EPI>
__global__ __launch_bounds__(256, 2)
void mma_gemm_kernel(const float* __restrict__ A, const float* __restrict__ Bm,
                     const float* __restrict__ bias, float* __restrict__ Cout,
                     int N, int K)
{
    __shared__ uint32_t As[2][128 * ASTR];
    __shared__ uint32_t Bs[2][16 * BSTR];

    const int tid   = threadIdx.x;
    const int lane  = tid & 31;
    const int warp  = tid >> 5;
    const int warpM = warp & 3;          // 0..3 -> m offset *32
    const int warpN = warp >> 2;         // 0..1 -> n offset *64
    const int g     = lane >> 2;         // 0..7
    const int t     = lane & 3;          // 0..3

    const int bm = blockIdx.y * 128;
    const int bn = blockIdx.x * 128;

    // Global-load coordinates (per thread: 2 float4 for A, 2 for B per stage)
    const int arow0 = tid >> 2;                  // 0..63
    const int acol  = (tid & 3) << 2;            // 0,4,8,12
    const int brow0 = tid >> 5;                  // 0..7
    const int bcol  = (tid & 31) << 2;           // 0..124

    float acc[2][8][4] = {};

    // ---- stage 0 ----
    {
        float4 a0 = *(const float4*)&A[(bm + arow0) * K + acol];
        float4 a1 = *(const float4*)&A[(bm + arow0 + 64) * K + acol];
        float4 b0 = *(const float4*)&Bm[brow0 * N + bn + bcol];
        float4 b1 = *(const float4*)&Bm[(brow0 + 8) * N + bn + bcol];
        uint32_t* as0 = &As[0][arow0 * ASTR + acol];
        uint32_t* as1 = &As[0][(arow0 + 64) * ASTR + acol];
        as0[0]=f2tf(a0.x); as0[1]=f2tf(a0.y); as0[2]=f2tf(a0.z); as0[3]=f2tf(a0.w);
        as1[0]=f2tf(a1.x); as1[1]=f2tf(a1.y); as1[2]=f2tf(a1.z); as1[3]=f2tf(a1.w);
        uint32_t* bs0 = &Bs[0][brow0 * BSTR + bcol];
        uint32_t* bs1 = &Bs[0][(brow0 + 8) * BSTR + bcol];
        bs0[0]=f2tf(b0.x); bs0[1]=f2tf(b0.y); bs0[2]=f2tf(b0.z); bs0[3]=f2tf(b0.w);
        bs1[0]=f2tf(b1.x); bs1[1]=f2tf(b1.y); bs1[2]=f2tf(b1.z); bs1[3]=f2tf(b1.w);
    }
    __syncthreads();

    int buf = 0;
    for (int k0 = 0; k0 < K; k0 += 16) {
        const bool has = (k0 + 16) < K;
        float4 pa0, pa1, pb0, pb1;
        if (has) {
            pa0 = *(const float4*)&A[(bm + arow0) * K + k0 + 16 + acol];
            pa1 = *(const float4*)&A[(bm + arow0 + 64) * K + k0 + 16 + acol];
            pb0 = *(const float4*)&Bm[(k0 + 16 + brow0) * N + bn + bcol];
            pb1 = *(const float4*)&Bm[(k0 + 16 + brow0 + 8) * N + bn + bcol];
        }

        // compute two k=8 steps on current buffer
        #pragma unroll
        for (int ks = 0; ks < 2; ks++) {
            const int ko = ks * 8;
            uint32_t af[2][4];
            uint32_t bf[8][2];
            #pragma unroll
            for (int mt = 0; mt < 2; mt++) {
                const int mb = warpM * 32 + mt * 16;
                af[mt][0] = As[buf][(mb + g)     * ASTR + ko + t];
                af[mt][1] = As[buf][(mb + g + 8) * ASTR + ko + t];
                af[mt][2] = As[buf][(mb + g)     * ASTR + ko + t + 4];
                af[mt][3] = As[buf][(mb + g + 8) * ASTR + ko + t + 4];
            }
            #pragma unroll
            for (int nt = 0; nt < 8; nt++) {
                const int nb = warpN * 64 + nt * 8;
                bf[nt][0] = Bs[buf][(ko + t)     * BSTR + nb + g];
                bf[nt][1] = Bs[buf][(ko + t + 4) * BSTR + nb + g];
            }
            #pragma unroll
            for (int mt = 0; mt < 2; mt++)
                #pragma unroll
                for (int nt = 0; nt < 8; nt++)
                    mma_tf32(acc[mt][nt], af[mt], bf[nt]);
        }

        if (has) {
            const int nxt = buf ^ 1;
            uint32_t* as0 = &As[nxt][arow0 * ASTR + acol];
            uint32_t* as1 = &As[nxt][(arow0 + 64) * ASTR + acol];
            as0[0]=f2tf(pa0.x); as0[1]=f2tf(pa0.y); as0[2]=f2tf(pa0.z); as0[3]=f2tf(pa0.w);
            as1[0]=f2tf(pa1.x); as1[1]=f2tf(pa1.y); as1[2]=f2tf(pa1.z); as1[3]=f2tf(pa1.w);
            uint32_t* bs0 = &Bs[nxt][brow0 * BSTR + bcol];
            uint32_t* bs1 = &Bs[nxt][(brow0 + 8) * BSTR + bcol];
            bs0[0]=f2tf(pb0.x); bs0[1]=f2tf(pb0.y); bs0[2]=f2tf(pb0.z); bs0[3]=f2tf(pb0.w);
            bs1[0]=f2tf(pb1.x); bs1[1]=f2tf(pb1.y); bs1[2]=f2tf(pb1.z); bs1[3]=f2tf(pb1.w);
        }
        __syncthreads();
        buf ^= 1;
    }

    // ---- epilogue ----
    #pragma unroll
    for (int mt = 0; mt < 2; mt++) {
        #pragma unroll
        for (int nt = 0; nt < 8; nt++) {
            const int row0 = bm + warpM * 32 + mt * 16 + g;
            const int col  = bn + warpN * 64 + nt * 8 + 2 * t;
            const float b0 = bias[col];
            const float b1 = bias[col + 1];
            float2 v0 = make_float2(acc[mt][nt][0] + b0, acc[mt][nt][1] + b1);
            float2 v1 = make_float2(acc[mt][nt][2] + b0, acc[mt][nt][3] + b1);
            if (EPI == 1) {
                *(float2*)&Cout[row0 * N + col]       = v0;
                *(float2*)&Cout[(row0 + 8) * N + col] = v1;
            } else {
                const int which = col >> 10;          // 0=q,1=k,2=v
                const int h     = (col >> 6) & 15;
                const int d     = col & 63;
                float* dst = (which == 0) ? g_Q : (which == 1) ? g_K : g_V;
                {
                    const int b = row0 >> 11, tt = row0 & 2047;
                    *(float2*)&dst[(((b << 4) + h) * TT + tt) * HD + d] = v0;
                }
                {
                    const int r1 = row0 + 8;
                    const int b = r1 >> 11, tt = r1 & 2047;
                    *(float2*)&dst[(((b << 4) + h) * TT + tt) * HD + d] = v1;
                }
            }
        }
    }
}

// ---------------------------------------------------------------------------
// Kernel 2: causal flash attention, fp32 (unchanged, proven correct).
// ---------------------------------------------------------------------------
__global__ __launch_bounds__(64)
void attn_kernel()
{
    const int bh   = blockIdx.y;
    const int b    = bh >> 4;
    const int h    = bh & 15;
    const int qblk = blockIdx.x;
    const int r    = threadIdx.x;
    const int m    = qblk * 64 + r;

    __shared__ float Ks[64 * 64];
    __shared__ float Vs[64 * 64];

    float q[64], o[64];
    const float* qrow = g_Q + (bh * TT + m) * HD;
    #pragma unroll
    for (int d4 = 0; d4 < 16; d4++) {
        float4 v = ((const float4*)qrow)[d4];
        q[d4 * 4 + 0] = v.x; q[d4 * 4 + 1] = v.y;
        q[d4 * 4 + 2] = v.z; q[d4 * 4 + 3] = v.w;
    }
    #pragma unroll
    for (int d = 0; d < 64; d++) o[d] = 0.f;

    float mi = -1e30f, li = 0.f;
    const float scale = 0.125f;

    #pragma unroll 1
    for (int jb = 0; jb <= qblk; jb++) {
        const float* kt = g_K + (bh * TT + jb * 64) * HD;
        const float* vt = g_V + (bh * TT + jb * 64) * HD;
        #pragma unroll
        for (int l = 0; l < 16; l++) {
            ((float4*)Ks)[r + l * 64] = ((const float4*)kt)[r + l * 64];
            ((float4*)Vs)[r + l * 64] = ((const float4*)vt)[r + l * 64];
        }
        __syncthreads();

        const int kbase = jb * 64;
        #pragma unroll
        for (int c = 0; c < 4; c++) {
            float s[16];
            #pragma unroll
            for (int kk = 0; kk < 16; kk++) {
                const int key = c * 16 + kk;
                float dot = 0.f;
                const float4* krow = (const float4*)(Ks + key * 64);
                #pragma unroll
                for (int d4 = 0; d4 < 16; d4++) {
                    float4 kv = krow[d4];
                    dot = fmaf(q[d4 * 4 + 0], kv.x, dot);
                    dot = fmaf(q[d4 * 4 + 1], kv.y, dot);
                    dot = fmaf(q[d4 * 4 + 2], kv.z, dot);
                    dot = fmaf(q[d4 * 4 + 3], kv.w, dot);
                }
                s[kk] = (kbase + key <= m) ? dot * scale : -1e30f;
            }
            float mnew = mi;
            #pragma unroll
            for (int kk = 0; kk < 16; kk++) mnew = fmaxf(mnew, s[kk]);
            const float alpha = __expf(mi - mnew);
            float ps = 0.f;
            #pragma unroll
            for (int kk = 0; kk < 16; kk++) {
                s[kk] = __expf(s[kk] - mnew);
                ps += s[kk];
            }
            li = li * alpha + ps;
            mi = mnew;
            #pragma unroll
            for (int d = 0; d < 64; d++) o[d] *= alpha;
            #pragma unroll
            for (int kk = 0; kk < 16; kk++) {
                const float p = s[kk];
                const float4* vrow = (const float4*)(Vs + (c * 16 + kk) * 64);
                #pragma unroll
                for (int d4 = 0; d4 < 16; d4++) {
                    float4 vv = vrow[d4];
                    o[d4 * 4 + 0] = fmaf(p, vv.x, o[d4 * 4 + 0]);
                    o[d4 * 4 + 1] = fmaf(p, vv.y, o[d4 * 4 + 1]);
                    o[d4 * 4 + 2] = fmaf(p, vv.z, o[d4 * 4 + 2]);
                    o[d4 * 4 + 3] = fmaf(p, vv.w, o[d4 * 4 + 3]);
                }
            }
        }
        __syncthreads();
    }

    const float inv = 1.f / li;
    float* yrow = g_Y + (b * TT + m) * DD + h * HD;
    #pragma unroll
    for (int d4 = 0; d4 < 16; d4++) {
        float4 v;
        v.x = o[d4 * 4 + 0] * inv;
        v.y = o[d4 * 4 + 1] * inv;
        v.z = o[d4 * 4 + 2] * inv;
        v.w = o[d4 * 4 + 3] * inv;
        ((float4*)yrow)[d4] = v;
    }
}

// ---------------------------------------------------------------------------
// Launch. Inputs: x, causal_mask(unused), w_qkv, b_qkv, w_out, b_out.
// ---------------------------------------------------------------------------
extern "C" void kernel_launch(void* const* d_in, const int* in_sizes, int n_in,
                              void* d_out, int out_size)
{
    const float* x     = (const float*)d_in[0];
    const float* w_qkv = (const float*)d_in[2];
    const float* b_qkv = (const float*)d_in[3];
    const float* w_out = (const float*)d_in[4];
    const float* b_out = (const float*)d_in[5];
    float* out = (float*)d_out;

    float* gy;
    cudaGetSymbolAddress((void**)&gy, g_Y);

    mma_gemm_kernel<0><<<dim3((3 * DD) / 128, BT / 128), 256>>>(
        x, w_qkv, b_qkv, nullptr, 3 * DD, DD);
    attn_kernel<<<dim3(TT / 64, BB * HH), 64>>>();
    mma_gemm_kernel<1><<<dim3(DD / 128, BT / 128), 256>>>(
        gy, w_out, b_out, out, DD, DD);
}

// round 3
// speedup vs baseline: 4.8220x; 3.5267x over previous
#include <cuda_runtime.h>
#include <cstdint>

// Problem constants
#define BB 4
#define TT 2048
#define DD 1024
#define HH 16
#define HD 64
#define BT (BB * TT)        // 8192

// Scratch (allocation-free rule: __device__ globals)
__device__ float g_Q[BB * HH * TT * HD];   // [B,H,T,HD]
__device__ float g_K[BB * HH * TT * HD];
__device__ float g_V[BB * HH * TT * HD];
__device__ float g_Y[BB * TT * DD];        // [B,T,D] attention output

__device__ __forceinline__ uint32_t f2tf(float f) {
    uint32_t u;
    asm("cvt.rna.tf32.f32 %0, %1;" : "=r"(u) : "f"(f));
    return u;
}

__device__ __forceinline__ void mma_tf32(float c[4], const uint32_t a[4],
                                         const uint32_t b0, const uint32_t b1) {
    asm volatile(
        "mma.sync.aligned.m16n8k8.row.col.f32.tf32.tf32.f32 "
        "{%0,%1,%2,%3}, {%4,%5,%6,%7}, {%8,%9}, {%0,%1,%2,%3};"
        : "+f"(c[0]), "+f"(c[1]), "+f"(c[2]), "+f"(c[3])
        : "r"(a[0]), "r"(a[1]), "r"(a[2]), "r"(a[3]), "r"(b0), "r"(b1));
}

// ---------------------------------------------------------------------------
// tf32 tensor-core GEMM (unchanged from round 2, validated).
// ---------------------------------------------------------------------------
#define ASTR 20
#define BSTR 132

template <int EPI>
__global__ __launch_bounds__(256, 2)
void mma_gemm_kernel(const float* __restrict__ A, const float* __restrict__ Bm,
                     const float* __restrict__ bias, float* __restrict__ Cout,
                     int N, int K)
{
    __shared__ uint32_t As[2][128 * ASTR];
    __shared__ uint32_t Bs[2][16 * BSTR];

    const int tid   = threadIdx.x;
    const int lane  = tid & 31;
    const int warp  = tid >> 5;
    const int warpM = warp & 3;
    const int warpN = warp >> 2;
    const int g     = lane >> 2;
    const int t     = lane & 3;

    const int bm = blockIdx.y * 128;
    const int bn = blockIdx.x * 128;

    const int arow0 = tid >> 2;
    const int acol  = (tid & 3) << 2;
    const int brow0 = tid >> 5;
    const int bcol  = (tid & 31) << 2;

    float acc[2][8][4] = {};

    {
        float4 a0 = *(const float4*)&A[(bm + arow0) * K + acol];
        float4 a1 = *(const float4*)&A[(bm + arow0 + 64) * K + acol];
        float4 b0 = *(const float4*)&Bm[brow0 * N + bn + bcol];
        float4 b1 = *(const float4*)&Bm[(brow0 + 8) * N + bn + bcol];
        uint32_t* as0 = &As[0][arow0 * ASTR + acol];
        uint32_t* as1 = &As[0][(arow0 + 64) * ASTR + acol];
        as0[0]=f2tf(a0.x); as0[1]=f2tf(a0.y); as0[2]=f2tf(a0.z); as0[3]=f2tf(a0.w);
        as1[0]=f2tf(a1.x); as1[1]=f2tf(a1.y); as1[2]=f2tf(a1.z); as1[3]=f2tf(a1.w);
        uint32_t* bs0 = &Bs[0][brow0 * BSTR + bcol];
        uint32_t* bs1 = &Bs[0][(brow0 + 8) * BSTR + bcol];
        bs0[0]=f2tf(b0.x); bs0[1]=f2tf(b0.y); bs0[2]=f2tf(b0.z); bs0[3]=f2tf(b0.w);
        bs1[0]=f2tf(b1.x); bs1[1]=f2tf(b1.y); bs1[2]=f2tf(b1.z); bs1[3]=f2tf(b1.w);
    }
    __syncthreads();

    int buf = 0;
    for (int k0 = 0; k0 < K; k0 += 16) {
        const bool has = (k0 + 16) < K;
        float4 pa0, pa1, pb0, pb1;
        if (has) {
            pa0 = *(const float4*)&A[(bm + arow0) * K + k0 + 16 + acol];
            pa1 = *(const float4*)&A[(bm + arow0 + 64) * K + k0 + 16 + acol];
            pb0 = *(const float4*)&Bm[(k0 + 16 + brow0) * N + bn + bcol];
            pb1 = *(const float4*)&Bm[(k0 + 16 + brow0 + 8) * N + bn + bcol];
        }

        #pragma unroll
        for (int ks = 0; ks < 2; ks++) {
            const int ko = ks * 8;
            uint32_t af[2][4];
            uint32_t bf[8][2];
            #pragma unroll
            for (int mt = 0; mt < 2; mt++) {
                const int mb = warpM * 32 + mt * 16;
                af[mt][0] = As[buf][(mb + g)     * ASTR + ko + t];
                af[mt][1] = As[buf][(mb + g + 8) * ASTR + ko + t];
                af[mt][2] = As[buf][(mb + g)     * ASTR + ko + t + 4];
                af[mt][3] = As[buf][(mb + g + 8) * ASTR + ko + t + 4];
            }
            #pragma unroll
            for (int nt = 0; nt < 8; nt++) {
                const int nb = warpN * 64 + nt * 8;
                bf[nt][0] = Bs[buf][(ko + t)     * BSTR + nb + g];
                bf[nt][1] = Bs[buf][(ko + t + 4) * BSTR + nb + g];
            }
            #pragma unroll
            for (int mt = 0; mt < 2; mt++)
                #pragma unroll
                for (int nt = 0; nt < 8; nt++)
                    mma_tf32(acc[mt][nt], af[mt], bf[nt][0], bf[nt][1]);
        }

        if (has) {
            const int nxt = buf ^ 1;
            uint32_t* as0 = &As[nxt][arow0 * ASTR + acol];
            uint32_t* as1 = &As[nxt][(arow0 + 64) * ASTR + acol];
            as0[0]=f2tf(pa0.x); as0[1]=f2tf(pa0.y); as0[2]=f2tf(pa0.z); as0[3]=f2tf(pa0.w);
            as1[0]=f2tf(pa1.x); as1[1]=f2tf(pa1.y); as1[2]=f2tf(pa1.z); as1[3]=f2tf(pa1.w);
            uint32_t* bs0 = &Bs[nxt][brow0 * BSTR + bcol];
            uint32_t* bs1 = &Bs[nxt][(brow0 + 8) * BSTR + bcol];
            bs0[0]=f2tf(pb0.x); bs0[1]=f2tf(pb0.y); bs0[2]=f2tf(pb0.z); bs0[3]=f2tf(pb0.w);
            bs1[0]=f2tf(pb1.x); bs1[1]=f2tf(pb1.y); bs1[2]=f2tf(pb1.z); bs1[3]=f2tf(pb1.w);
        }
        __syncthreads();
        buf ^= 1;
    }

    #pragma unroll
    for (int mt = 0; mt < 2; mt++) {
        #pragma unroll
        for (int nt = 0; nt < 8; nt++) {
            const int row0 = bm + warpM * 32 + mt * 16 + g;
            const int col  = bn + warpN * 64 + nt * 8 + 2 * t;
            const float b0 = bias[col];
            const float b1 = bias[col + 1];
            float2 v0 = make_float2(acc[mt][nt][0] + b0, acc[mt][nt][1] + b1);
            float2 v1 = make_float2(acc[mt][nt][2] + b0, acc[mt][nt][3] + b1);
            if (EPI == 1) {
                *(float2*)&Cout[row0 * N + col]       = v0;
                *(float2*)&Cout[(row0 + 8) * N + col] = v1;
            } else {
                const int which = col >> 10;
                const int h     = (col >> 6) & 15;
                const int d     = col & 63;
                float* dst = (which == 0) ? g_Q : (which == 1) ? g_K : g_V;
                {
                    const int b = row0 >> 11, tt = row0 & 2047;
                    *(float2*)&dst[(((b << 4) + h) * TT + tt) * HD + d] = v0;
                }
                {
                    const int r1 = row0 + 8;
                    const int b = r1 >> 11, tt = r1 & 2047;
                    *(float2*)&dst[(((b << 4) + h) * TT + tt) * HD + d] = v1;
                }
            }
        }
    }
}

// ---------------------------------------------------------------------------
// Kernel 2: causal flash attention via tf32 mma.
// Grid (T/64, B*H), 128 threads = 4 warps; warp w owns query rows
// qblk*64 + 16w .. +15. K/V tiles (64x64) in smem as tf32, strides chosen
// bank-conflict-free for the mma fragment access patterns.
// ---------------------------------------------------------------------------
#define KSTR 68   // Ks [key][dim]: B-frag addr g*68+t -> banks 4g+t unique
#define VSTR 72   // Vs [key][dim]: B-frag addr t*72+g -> banks 8t+g unique
#define PSTR 68   // Ps [row][key]: A-frag addr g*68+t -> banks 4g+t unique
#define ATTN_SMEM_BYTES ((64 * KSTR + 64 * VSTR + 4 * 16 * PSTR) * 4)

__global__ __launch_bounds__(128)
void attn_mma_kernel()
{
    extern __shared__ uint32_t dyn[];
    uint32_t* Ks = dyn;                       // 64 * KSTR
    uint32_t* Vs = Ks + 64 * KSTR;            // 64 * VSTR
    uint32_t* Ps = Vs + 64 * VSTR;            // 4 * 16 * PSTR

    const int bh   = blockIdx.y;              // b*H + h
    const int b    = bh >> 4;
    const int h    = bh & 15;
    const int qblk = blockIdx.x;
    const int tid  = threadIdx.x;
    const int lane = tid & 31;
    const int warp = tid >> 5;
    const int g    = lane >> 2;               // 0..7
    const int t    = lane & 3;                // 0..3
    uint32_t* Pw   = Ps + warp * 16 * PSTR;

    // ---- stage Q tile through Ks, pull fragments into registers ----
    {
        const float* qt = g_Q + (bh * TT + qblk * 64) * HD;
        #pragma unroll
        for (int l = 0; l < 8; l++) {
            const int idx  = tid + l * 128;   // 0..1023
            const int row  = idx >> 4;
            const int col4 = (idx & 15) << 2;
            float4 v = *(const float4*)&qt[row * HD + col4];
            uint32_t* d = &Ks[row * KSTR + col4];
            d[0]=f2tf(v.x); d[1]=f2tf(v.y); d[2]=f2tf(v.z); d[3]=f2tf(v.w);
        }
    }
    __syncthreads();
    uint32_t qf[8][4];
    {
        const int mb = warp * 16;
        #pragma unroll
        for (int c = 0; c < 8; c++) {
            qf[c][0] = Ks[(mb + g)     * KSTR + c * 8 + t];
            qf[c][1] = Ks[(mb + g + 8) * KSTR + c * 8 + t];
            qf[c][2] = Ks[(mb + g)     * KSTR + c * 8 + t + 4];
            qf[c][3] = Ks[(mb + g + 8) * KSTR + c * 8 + t + 4];
        }
    }

    float o[8][4] = {};                       // [dim-frag][c-layout]
    float mi0 = -1e30f, mi1 = -1e30f, li0 = 0.f, li1 = 0.f;
    const int row0 = qblk * 64 + warp * 16 + g;
    const int row1 = row0 + 8;
    const float scale = 0.125f;               // 1/sqrt(64)

    #pragma unroll 1
    for (int jb = 0; jb <= qblk; jb++) {
        __syncthreads();                      // all warps done with Ks/Vs
        {
            const float* kt = g_K + (bh * TT + jb * 64) * HD;
            const float* vt = g_V + (bh * TT + jb * 64) * HD;
            #pragma unroll
            for (int l = 0; l < 8; l++) {
                const int idx  = tid + l * 128;
                const int row  = idx >> 4;
                const int col4 = (idx & 15) << 2;
                float4 kv = *(const float4*)&kt[row * HD + col4];
                float4 vv = *(const float4*)&vt[row * HD + col4];
                uint32_t* dk = &Ks[row * KSTR + col4];
                dk[0]=f2tf(kv.x); dk[1]=f2tf(kv.y); dk[2]=f2tf(kv.z); dk[3]=f2tf(kv.w);
                uint32_t* dv = &Vs[row * VSTR + col4];
                dv[0]=f2tf(vv.x); dv[1]=f2tf(vv.y); dv[2]=f2tf(vv.z); dv[3]=f2tf(vv.w);
            }
        }
        __syncthreads();

        // ---- scores S = Q @ K^T : 8 n-frags of 8 keys ----
        float s[8][4] = {};
        #pragma unroll
        for (int c = 0; c < 8; c++) {         // dim chunks
            #pragma unroll
            for (int nf = 0; nf < 8; nf++) {  // key frags
                const uint32_t b0 = Ks[(nf * 8 + g) * KSTR + c * 8 + t];
                const uint32_t b1 = Ks[(nf * 8 + g) * KSTR + c * 8 + t + 4];
                mma_tf32(s[nf], qf[c], b0, b1);
            }
        }

        // ---- scale + causal mask ----
        if (jb == qblk) {
            #pragma unroll
            for (int nf = 0; nf < 8; nf++) {
                const int c0 = jb * 64 + nf * 8 + 2 * t;
                s[nf][0] = (c0     <= row0) ? s[nf][0] * scale : -1e30f;
                s[nf][1] = (c0 + 1 <= row0) ? s[nf][1] * scale : -1e30f;
                s[nf][2] = (c0     <= row1) ? s[nf][2] * scale : -1e30f;
                s[nf][3] = (c0 + 1 <= row1) ? s[nf][3] * scale : -1e30f;
            }
        } else {
            #pragma unroll
            for (int nf = 0; nf < 8; nf++) {
                s[nf][0] *= scale; s[nf][1] *= scale;
                s[nf][2] *= scale; s[nf][3] *= scale;
            }
        }

        // ---- online softmax (fp32) ----
        float lm0 = -1e30f, lm1 = -1e30f;
        #pragma unroll
        for (int nf = 0; nf < 8; nf++) {
            lm0 = fmaxf(lm0, fmaxf(s[nf][0], s[nf][1]));
            lm1 = fmaxf(lm1, fmaxf(s[nf][2], s[nf][3]));
        }
        lm0 = fmaxf(lm0, __shfl_xor_sync(0xffffffffu, lm0, 1));
        lm0 = fmaxf(lm0, __shfl_xor_sync(0xffffffffu, lm0, 2));
        lm1 = fmaxf(lm1, __shfl_xor_sync(0xffffffffu, lm1, 1));
        lm1 = fmaxf(lm1, __shfl_xor_sync(0xffffffffu, lm1, 2));
        const float mn0 = fmaxf(mi0, lm0);
        const float mn1 = fmaxf(mi1, lm1);
        const float a0 = __expf(mi0 - mn0);
        const float a1 = __expf(mi1 - mn1);
        float ls0 = 0.f, ls1 = 0.f;
        #pragma unroll
        for (int nf = 0; nf < 8; nf++) {
            s[nf][0] = __expf(s[nf][0] - mn0); ls0 += s[nf][0];
            s[nf][1] = __expf(s[nf][1] - mn0); ls0 += s[nf][1];
            s[nf][2] = __expf(s[nf][2] - mn1); ls1 += s[nf][2];
            s[nf][3] = __expf(s[nf][3] - mn1); ls1 += s[nf][3];
        }
        ls0 += __shfl_xor_sync(0xffffffffu, ls0, 1);
        ls0 += __shfl_xor_sync(0xffffffffu, ls0, 2);
        ls1 += __shfl_xor_sync(0xffffffffu, ls1, 1);
        ls1 += __shfl_xor_sync(0xffffffffu, ls1, 2);
        li0 = li0 * a0 + ls0;  mi0 = mn0;
        li1 = li1 * a1 + ls1;  mi1 = mn1;
        #pragma unroll
        for (int nf = 0; nf < 8; nf++) {
            o[nf][0] *= a0; o[nf][1] *= a0;
            o[nf][2] *= a1; o[nf][3] *= a1;
        }

        // ---- P -> per-warp smem (C-layout -> A-layout route) ----
        #pragma unroll
        for (int nf = 0; nf < 8; nf++) {
            *(uint2*)&Pw[g       * PSTR + nf * 8 + 2 * t] =
                make_uint2(f2tf(s[nf][0]), f2tf(s[nf][1]));
            *(uint2*)&Pw[(g + 8) * PSTR + nf * 8 + 2 * t] =
                make_uint2(f2tf(s[nf][2]), f2tf(s[nf][3]));
        }
        __syncwarp();

        // ---- O += P @ V ----
        #pragma unroll
        for (int kc = 0; kc < 8; kc++) {      // key chunks
            uint32_t af[4];
            af[0] = Pw[g       * PSTR + kc * 8 + t];
            af[1] = Pw[(g + 8) * PSTR + kc * 8 + t];
            af[2] = Pw[g       * PSTR + kc * 8 + t + 4];
            af[3] = Pw[(g + 8) * PSTR + kc * 8 + t + 4];
            #pragma unroll
            for (int nf = 0; nf < 8; nf++) {  // dim frags
                const uint32_t b0 = Vs[(kc * 8 + t)     * VSTR + nf * 8 + g];
                const uint32_t b1 = Vs[(kc * 8 + t + 4) * VSTR + nf * 8 + g];
                mma_tf32(o[nf], af, b0, b1);
            }
        }
    }

    // ---- normalize + write [B,T,D] ----
    const float inv0 = 1.f / li0;
    const float inv1 = 1.f / li1;
    float* y0 = g_Y + (b * TT + row0) * DD + h * HD;
    float* y1 = g_Y + (b * TT + row1) * DD + h * HD;
    #pragma unroll
    for (int nf = 0; nf < 8; nf++) {
        const int col = nf * 8 + 2 * t;
        *(float2*)&y0[col] = make_float2(o[nf][0] * inv0, o[nf][1] * inv0);
        *(float2*)&y1[col] = make_float2(o[nf][2] * inv1, o[nf][3] * inv1);
    }
}

// ---------------------------------------------------------------------------
// Launch. Inputs: x, causal_mask(unused), w_qkv, b_qkv, w_out, b_out.
// ---------------------------------------------------------------------------
extern "C" void kernel_launch(void* const* d_in, const int* in_sizes, int n_in,
                              void* d_out, int out_size)
{
    const float* x     = (const float*)d_in[0];
    const float* w_qkv = (const float*)d_in[2];
    const float* b_qkv = (const float*)d_in[3];
    const float* w_out = (const float*)d_in[4];
    const float* b_out = (const float*)d_in[5];
    float* out = (float*)d_out;

    float* gy;
    cudaGetSymbolAddress((void**)&gy, g_Y);
    cudaFuncSetAttribute(attn_mma_kernel,
                         cudaFuncAttributeMaxDynamicSharedMemorySize,
                         ATTN_SMEM_BYTES);

    mma_gemm_kernel<0><<<dim3((3 * DD) / 128, BT / 128), 256>>>(
        x, w_qkv, b_qkv, nullptr, 3 * DD, DD);
    attn_mma_kernel<<<dim3(TT / 64, BB * HH), 128, ATTN_SMEM_BYTES>>>();
    mma_gemm_kernel<1><<<dim3(DD / 128, BT / 128), 256>>>(
        gy, w_out, b_out, out, DD, DD);
}

// round 5
// speedup vs baseline: 5.0359x; 1.0444x over previous
#include <cuda_runtime.h>
#include <cstdint>

// Problem constants
#define BB 4
#define TT 2048
#define DD 1024
#define HH 16
#define HD 64
#define BT (BB * TT)        // 8192

// tf32 scratch (allocation-free rule: __device__ globals), all uint32 bit-patterns
__device__ uint32_t g_xt[BT * DD];            // x as tf32
__device__ uint32_t g_wqkvt[DD * 3 * DD];     // w_qkv as tf32
__device__ uint32_t g_wot[DD * DD];           // w_out as tf32
__device__ uint32_t g_Qt[BB * HH * TT * HD];  // [B,H,T,HD] tf32, pre-scaled by 0.125
__device__ uint32_t g_Kt[BB * HH * TT * HD];
__device__ uint32_t g_Vt[BB * HH * TT * HD];
__device__ uint32_t g_Yt[BT * DD];            // [B,T,D] attention out, tf32

__device__ __forceinline__ uint32_t f2tf(float f) {
    uint32_t u;
    asm("cvt.rna.tf32.f32 %0, %1;" : "=r"(u) : "f"(f));
    return u;
}

__device__ __forceinline__ void mma_tf32(float c[4], const uint32_t a[4],
                                         const uint32_t b0, const uint32_t b1) {
    asm volatile(
        "mma.sync.aligned.m16n8k8.row.col.f32.tf32.tf32.f32 "
        "{%0,%1,%2,%3}, {%4,%5,%6,%7}, {%8,%9}, {%0,%1,%2,%3};"
        : "+f"(c[0]), "+f"(c[1]), "+f"(c[2]), "+f"(c[3])
        : "r"(a[0]), "r"(a[1]), "r"(a[2]), "r"(a[3]), "r"(b0), "r"(b1));
}

__device__ __forceinline__ void cp16(uint32_t smem_addr, const void* gptr) {
    asm volatile("cp.async.cg.shared.global [%0], [%1], 16;\n"
                 :: "r"(smem_addr), "l"(gptr));
}
__device__ __forceinline__ void cp_commit() {
    asm volatile("cp.async.commit_group;\n");
}
template <int N>
__device__ __forceinline__ void cp_wait() {
    asm volatile("cp.async.wait_group %0;\n" :: "n"(N));
}

// ---------------------------------------------------------------------------
// Pre-convert fp32 -> tf32 (elementwise, float4)
// ---------------------------------------------------------------------------
__global__ void cvt_tf32_kernel(const float4* __restrict__ s,
                                uint4* __restrict__ d, int n4)
{
    int i = blockIdx.x * blockDim.x + threadIdx.x;
    if (i < n4) {
        float4 v = s[i];
        d[i] = make_uint4(f2tf(v.x), f2tf(v.y), f2tf(v.z), f2tf(v.w));
    }
}

// ---------------------------------------------------------------------------
// tf32 tensor-core GEMM, cp.async 3-stage pipeline.
// C[M,N] = A[M,K] @ B[K,N] + bias.  CTA 128x128, BK=16, 256 thr, 8 warps.
// A,B already tf32. EPI=0: scatter tf32 to g_Qt/g_Kt/g_Vt (Q scaled 0.125).
// EPI=1: fp32 dense write to Cout.
// ---------------------------------------------------------------------------
#define ASTR 20
#define BSTR 132
#define STAGES 3
#define GEMM_SMEM ((STAGES * 128 * ASTR + STAGES * 16 * BSTR) * 4)

template <int EPI>
__global__ __launch_bounds__(256, 2)
void mma_gemm_kernel(const uint32_t* __restrict__ A,
                     const uint32_t* __restrict__ Bm,
                     const float* __restrict__ bias, float* __restrict__ Cout,
                     int N, int K)
{
    extern __shared__ uint32_t gsm[];
    uint32_t* As = gsm;                          // STAGES * 128 * ASTR
    uint32_t* Bs = gsm + STAGES * 128 * ASTR;    // STAGES * 16 * BSTR

    const int tid   = threadIdx.x;
    const int lane  = tid & 31;
    const int warp  = tid >> 5;
    const int warpM = warp & 3;
    const int warpN = warp >> 2;
    const int g     = lane >> 2;
    const int t     = lane & 3;

    const int bm = blockIdx.y * 128;
    const int bn = blockIdx.x * 128;

    const int arow0 = tid >> 2;                  // 0..63
    const int acol  = (tid & 3) << 2;            // 0,4,8,12
    const int brow0 = tid >> 5;                  // 0..7
    const int bcol  = (tid & 31) << 2;           // 0..124

    const int iters = K >> 4;                    // 64

    auto issue = [&](int st, int k0) {
        uint32_t* as = As + st * 128 * ASTR;
        uint32_t* bs = Bs + st * 16 * BSTR;
        cp16((uint32_t)__cvta_generic_to_shared(&as[arow0 * ASTR + acol]),
             &A[(bm + arow0) * K + k0 + acol]);
        cp16((uint32_t)__cvta_generic_to_shared(&as[(arow0 + 64) * ASTR + acol]),
             &A[(bm + arow0 + 64) * K + k0 + acol]);
        cp16((uint32_t)__cvta_generic_to_shared(&bs[brow0 * BSTR + bcol]),
             &Bm[(k0 + brow0) * N + bn + bcol]);
        cp16((uint32_t)__cvta_generic_to_shared(&bs[(brow0 + 8) * BSTR + bcol]),
             &Bm[(k0 + brow0 + 8) * N + bn + bcol]);
    };

    float acc[2][8][4] = {};

    issue(0, 0);  cp_commit();
    issue(1, 16); cp_commit();

    for (int it = 0; it < iters; it++) {
        cp_wait<1>();
        __syncthreads();

        if (it + 2 < iters) issue((it + 2) % STAGES, (it + 2) * 16);
        cp_commit();

        const uint32_t* as = As + (it % STAGES) * 128 * ASTR;
        const uint32_t* bs = Bs + (it % STAGES) * 16 * BSTR;

        #pragma unroll
        for (int ks = 0; ks < 2; ks++) {
            const int ko = ks * 8;
            uint32_t af[2][4];
            uint32_t bf[8][2];
            #pragma unroll
            for (int mt = 0; mt < 2; mt++) {
                const int mb = warpM * 32 + mt * 16;
                af[mt][0] = as[(mb + g)     * ASTR + ko + t];
                af[mt][1] = as[(mb + g + 8) * ASTR + ko + t];
                af[mt][2] = as[(mb + g)     * ASTR + ko + t + 4];
                af[mt][3] = as[(mb + g + 8) * ASTR + ko + t + 4];
            }
            #pragma unroll
            for (int nt = 0; nt < 8; nt++) {
                const int nb = warpN * 64 + nt * 8;
                bf[nt][0] = bs[(ko + t)     * BSTR + nb + g];
                bf[nt][1] = bs[(ko + t + 4) * BSTR + nb + g];
            }
            #pragma unroll
            for (int mt = 0; mt < 2; mt++)
                #pragma unroll
                for (int nt = 0; nt < 8; nt++)
                    mma_tf32(acc[mt][nt], af[mt], bf[nt][0], bf[nt][1]);
        }
        __syncthreads();
    }

    // ---- epilogue ----
    #pragma unroll
    for (int mt = 0; mt < 2; mt++) {
        #pragma unroll
        for (int nt = 0; nt < 8; nt++) {
            const int row0 = bm + warpM * 32 + mt * 16 + g;
            const int col  = bn + warpN * 64 + nt * 8 + 2 * t;
            const float b0 = bias[col];
            const float b1 = bias[col + 1];
            float2 v0 = make_float2(acc[mt][nt][0] + b0, acc[mt][nt][1] + b1);
            float2 v1 = make_float2(acc[mt][nt][2] + b0, acc[mt][nt][3] + b1);
            if (EPI == 1) {
                *(float2*)&Cout[row0 * N + col]       = v0;
                *(float2*)&Cout[(row0 + 8) * N + col] = v1;
            } else {
                const int which = col >> 10;          // 0=q,1=k,2=v
                const int h     = (col >> 6) & 15;
                const int d     = col & 63;
                uint32_t* dst = (which == 0) ? g_Qt : (which == 1) ? g_Kt : g_Vt;
                const float sc = (which == 0) ? 0.125f : 1.0f;
                {
                    const int b = row0 >> 11, tt = row0 & 2047;
                    *(uint2*)&dst[(((b << 4) + h) * TT + tt) * HD + d] =
                        make_uint2(f2tf(v0.x * sc), f2tf(v0.y * sc));
                }
                {
                    const int r1 = row0 + 8;
                    const int b = r1 >> 11, tt = r1 & 2047;
                    *(uint2*)&dst[(((b << 4) + h) * TT + tt) * HD + d] =
                        make_uint2(f2tf(v1.x * sc), f2tf(v1.y * sc));
                }
            }
        }
    }
}

// ---------------------------------------------------------------------------
// Causal flash attention, tf32 mma, 2-stage cp.async K/V pipeline.
// Grid (T/64, B*H), 128 threads = 4 warps; warp w owns rows qblk*64+16w..+15.
// Q/K/V already tf32 in global (Q pre-scaled). Output written as tf32 g_Yt.
// ---------------------------------------------------------------------------
#define KSTR 68
#define VSTR 72
#define PSTR 68
#define ATTN_SMEM_BYTES ((2 * 64 * KSTR + 2 * 64 * VSTR + 4 * 16 * PSTR) * 4)

__global__ __launch_bounds__(128)
void attn_mma_kernel()
{
    extern __shared__ uint32_t dyn[];
    uint32_t* KsB = dyn;                          // 2 * 64*KSTR
    uint32_t* VsB = KsB + 2 * 64 * KSTR;          // 2 * 64*VSTR
    uint32_t* Ps  = VsB + 2 * 64 * VSTR;          // 4 * 16*PSTR

    const int bh   = blockIdx.y;
    const int b    = bh >> 4;
    const int h    = bh & 15;
    const int qblk = blockIdx.x;
    const int tid  = threadIdx.x;
    const int lane = tid & 31;
    const int warp = tid >> 5;
    const int g    = lane >> 2;
    const int t    = lane & 3;
    uint32_t* Pw   = Ps + warp * 16 * PSTR;

    // FIXED loader: full 64x64 tile (8 iters x 128 thr x float4 = 1024 float4)
    auto issue_kv = [&](int st, int jb) {
        const uint32_t* kt = g_Kt + (bh * TT + jb * 64) * HD;
        const uint32_t* vt = g_Vt + (bh * TT + jb * 64) * HD;
        uint32_t* ks = KsB + st * 64 * KSTR;
        uint32_t* vs = VsB + st * 64 * VSTR;
        #pragma unroll
        for (int l = 0; l < 8; l++) {
            const int idx  = tid + l * 128;       // 0..1023
            const int row  = idx >> 4;            // 0..63
            const int col4 = (idx & 15) << 2;     // 0..60
            cp16((uint32_t)__cvta_generic_to_shared(&ks[row * KSTR + col4]),
                 &kt[row * HD + col4]);
            cp16((uint32_t)__cvta_generic_to_shared(&vs[row * VSTR + col4]),
                 &vt[row * HD + col4]);
        }
    };

    // ---- stage this warp's Q rows through Pw, pull fragments ----
    uint32_t qf[8][4];
    {
        const uint32_t* qt = g_Qt + (bh * TT + qblk * 64 + warp * 16) * HD;
        #pragma unroll
        for (int l = 0; l < 8; l++) {
            const int idx  = lane + l * 32;       // 0..255
            const int row  = idx >> 4;            // 0..15
            const int c4   = (idx & 15) << 2;
            *(uint4*)&Pw[row * PSTR + c4] = *(const uint4*)&qt[row * HD + c4];
        }
        __syncwarp();
        #pragma unroll
        for (int c = 0; c < 8; c++) {
            qf[c][0] = Pw[g       * PSTR + c * 8 + t];
            qf[c][1] = Pw[(g + 8) * PSTR + c * 8 + t];
            qf[c][2] = Pw[g       * PSTR + c * 8 + t + 4];
            qf[c][3] = Pw[(g + 8) * PSTR + c * 8 + t + 4];
        }
        __syncwarp();
    }

    float o[8][4] = {};
    float mi0 = -1e30f, mi1 = -1e30f, li0 = 0.f, li1 = 0.f;
    const int row0 = qblk * 64 + warp * 16 + g;
    const int row1 = row0 + 8;

    issue_kv(0, 0);
    cp_commit();

    #pragma unroll 1
    for (int jb = 0; jb <= qblk; jb++) {
        if (jb + 1 <= qblk) issue_kv((jb + 1) & 1, jb + 1);
        cp_commit();
        cp_wait<1>();
        __syncthreads();

        const uint32_t* Ks = KsB + (jb & 1) * 64 * KSTR;
        const uint32_t* Vs = VsB + (jb & 1) * 64 * VSTR;

        // ---- S = Q @ K^T (Q pre-scaled) ----
        float s[8][4] = {};
        #pragma unroll
        for (int c = 0; c < 8; c++) {
            #pragma unroll
            for (int nf = 0; nf < 8; nf++) {
                const uint32_t b0 = Ks[(nf * 8 + g) * KSTR + c * 8 + t];
                const uint32_t b1 = Ks[(nf * 8 + g) * KSTR + c * 8 + t + 4];
                mma_tf32(s[nf], qf[c], b0, b1);
            }
        }

        // ---- causal mask (diagonal tile only) ----
        if (jb == qblk) {
            #pragma unroll
            for (int nf = 0; nf < 8; nf++) {
                const int c0 = jb * 64 + nf * 8 + 2 * t;
                if (c0     > row0) s[nf][0] = -1e30f;
                if (c0 + 1 > row0) s[nf][1] = -1e30f;
                if (c0     > row1) s[nf][2] = -1e30f;
                if (c0 + 1 > row1) s[nf][3] = -1e30f;
            }
        }

        // ---- online softmax (fp32) ----
        float lm0 = -1e30f, lm1 = -1e30f;
        #pragma unroll
        for (int nf = 0; nf < 8; nf++) {
            lm0 = fmaxf(lm0, fmaxf(s[nf][0], s[nf][1]));
            lm1 = fmaxf(lm1, fmaxf(s[nf][2], s[nf][3]));
        }
        lm0 = fmaxf(lm0, __shfl_xor_sync(0xffffffffu, lm0, 1));
        lm0 = fmaxf(lm0, __shfl_xor_sync(0xffffffffu, lm0, 2));
        lm1 = fmaxf(lm1, __shfl_xor_sync(0xffffffffu, lm1, 1));
        lm1 = fmaxf(lm1, __shfl_xor_sync(0xffffffffu, lm1, 2));
        const float mn0 = fmaxf(mi0, lm0);
        const float mn1 = fmaxf(mi1, lm1);
        const float a0 = __expf(mi0 - mn0);
        const float a1 = __expf(mi1 - mn1);
        float ls0 = 0.f, ls1 = 0.f;
        #pragma unroll
        for (int nf = 0; nf < 8; nf++) {
            s[nf][0] = __expf(s[nf][0] - mn0); ls0 += s[nf][0];
            s[nf][1] = __expf(s[nf][1] - mn0); ls0 += s[nf][1];
            s[nf][2] = __expf(s[nf][2] - mn1); ls1 += s[nf][2];
            s[nf][3] = __expf(s[nf][3] - mn1); ls1 += s[nf][3];
        }
        ls0 += __shfl_xor_sync(0xffffffffu, ls0, 1);
        ls0 += __shfl_xor_sync(0xffffffffu, ls0, 2);
        ls1 += __shfl_xor_sync(0xffffffffu, ls1, 1);
        ls1 += __shfl_xor_sync(0xffffffffu, ls1, 2);
        li0 = li0 * a0 + ls0;  mi0 = mn0;
        li1 = li1 * a1 + ls1;  mi1 = mn1;
        #pragma unroll
        for (int nf = 0; nf < 8; nf++) {
            o[nf][0] *= a0; o[nf][1] *= a0;
            o[nf][2] *= a1; o[nf][3] *= a1;
        }

        // ---- P -> per-warp smem (C-layout -> A-layout) ----
        #pragma unroll
        for (int nf = 0; nf < 8; nf++) {
            *(uint2*)&Pw[g       * PSTR + nf * 8 + 2 * t] =
                make_uint2(f2tf(s[nf][0]), f2tf(s[nf][1]));
            *(uint2*)&Pw[(g + 8) * PSTR + nf * 8 + 2 * t] =
                make_uint2(f2tf(s[nf][2]), f2tf(s[nf][3]));
        }
        __syncwarp();

        // ---- O += P @ V ----
        #pragma unroll
        for (int kc = 0; kc < 8; kc++) {
            uint32_t af[4];
            af[0] = Pw[g       * PSTR + kc * 8 + t];
            af[1] = Pw[(g + 8) * PSTR + kc * 8 + t];
            af[2] = Pw[g       * PSTR + kc * 8 + t + 4];
            af[3] = Pw[(g + 8) * PSTR + kc * 8 + t + 4];
            #pragma unroll
            for (int nf = 0; nf < 8; nf++) {
                const uint32_t b0 = Vs[(kc * 8 + t)     * VSTR + nf * 8 + g];
                const uint32_t b1 = Vs[(kc * 8 + t + 4) * VSTR + nf * 8 + g];
                mma_tf32(o[nf], af, b0, b1);
            }
        }
        __syncthreads();   // all warps done with this K/V stage before reuse
    }

    // ---- normalize + write tf32 [B,T,D] ----
    const float inv0 = 1.f / li0;
    const float inv1 = 1.f / li1;
    uint32_t* y0 = g_Yt + (b * TT + row0) * DD + h * HD;
    uint32_t* y1 = g_Yt + (b * TT + row1) * DD + h * HD;
    #pragma unroll
    for (int nf = 0; nf < 8; nf++) {
        const int col = nf * 8 + 2 * t;
        *(uint2*)&y0[col] = make_uint2(f2tf(o[nf][0] * inv0), f2tf(o[nf][1] * inv0));
        *(uint2*)&y1[col] = make_uint2(f2tf(o[nf][2] * inv1), f2tf(o[nf][3] * inv1));
    }
}

// ---------------------------------------------------------------------------
// Launch. Inputs: x, causal_mask(unused), w_qkv, b_qkv, w_out, b_out.
// ---------------------------------------------------------------------------
extern "C" void kernel_launch(void* const* d_in, const int* in_sizes, int n_in,
                              void* d_out, int out_size)
{
    const float* x     = (const float*)d_in[0];
    const float* w_qkv = (const float*)d_in[2];
    const float* b_qkv = (const float*)d_in[3];
    const float* w_out = (const float*)d_in[4];
    const float* b_out = (const float*)d_in[5];
    float* out = (float*)d_out;

    uint32_t *xt, *wqkvt, *wot, *yt;
    cudaGetSymbolAddress((void**)&xt,    g_xt);
    cudaGetSymbolAddress((void**)&wqkvt, g_wqkvt);
    cudaGetSymbolAddress((void**)&wot,   g_wot);
    cudaGetSymbolAddress((void**)&yt,    g_Yt);

    cudaFuncSetAttribute(mma_gemm_kernel<0>,
                         cudaFuncAttributeMaxDynamicSharedMemorySize, GEMM_SMEM);
    cudaFuncSetAttribute(mma_gemm_kernel<1>,
                         cudaFuncAttributeMaxDynamicSharedMemorySize, GEMM_SMEM);
    cudaFuncSetAttribute(attn_mma_kernel,
                         cudaFuncAttributeMaxDynamicSharedMemorySize,
                         ATTN_SMEM_BYTES);

    // pre-convert inputs/weights to tf32
    cvt_tf32_kernel<<<(BT * DD / 4 + 255) / 256, 256>>>(
        (const float4*)x, (uint4*)xt, BT * DD / 4);
    cvt_tf32_kernel<<<(DD * 3 * DD / 4 + 255) / 256, 256>>>(
        (const float4*)w_qkv, (uint4*)wqkvt, DD * 3 * DD / 4);
    cvt_tf32_kernel<<<(DD * DD / 4 + 255) / 256, 256>>>(
        (const float4*)w_out, (uint4*)wot, DD * DD / 4);

    mma_gemm_kernel<0><<<dim3((3 * DD) / 128, BT / 128), 256, GEMM_SMEM>>>(
        xt, wqkvt, b_qkv, nullptr, 3 * DD, DD);
    attn_mma_kernel<<<dim3(TT / 64, BB * HH), 128, ATTN_SMEM_BYTES>>>();
    mma_gemm_kernel<1><<<dim3(DD / 128, BT / 128), 256, GEMM_SMEM>>>(
        yt, wot, b_out, out, DD, DD);
}

// round 6
// speedup vs baseline: 9.7838x; 1.9428x over previous
#include <cuda_runtime.h>
#include <cuda_fp16.h>
#include <cstdint>

// Problem constants
#define BB 4
#define TT 2048
#define DD 1024
#define HH 16
#define HD 64
#define BT (BB * TT)        // 8192

// fp16 scratch (allocation-free rule: __device__ globals); uint32 = packed half2
__device__ uint32_t g_xh[BT * DD / 2];             // x  [m][kpair]
__device__ uint32_t g_wqkvh[(DD / 2) * 3 * DD];    // w_qkv packed-T [kpair][n]
__device__ uint32_t g_woh[(DD / 2) * DD];          // w_out packed-T [kpair][n]
__device__ uint32_t g_Qh[BB * HH * TT * HD / 2];   // [B,H,T,HDpair], pre-scaled 0.125
__device__ uint32_t g_Kh[BB * HH * TT * HD / 2];   // [B,H,T,HDpair]
__device__ __half   g_Vth[BB * HH * HD * TT];      // V transposed [B,H,HD,T]
__device__ uint32_t g_Yh[BT * DD / 2];             // attn out [B,T,Dpair]

__device__ __forceinline__ uint32_t pack2(float a, float b) {
    __half2 h = __floats2half2_rn(a, b);
    return *(uint32_t*)&h;
}

__device__ __forceinline__ void mma_f16(float c[4], const uint32_t a[4],
                                        const uint32_t b0, const uint32_t b1) {
    asm volatile(
        "mma.sync.aligned.m16n8k16.row.col.f32.f16.f16.f32 "
        "{%0,%1,%2,%3}, {%4,%5,%6,%7}, {%8,%9}, {%0,%1,%2,%3};"
        : "+f"(c[0]), "+f"(c[1]), "+f"(c[2]), "+f"(c[3])
        : "r"(a[0]), "r"(a[1]), "r"(a[2]), "r"(a[3]), "r"(b0), "r"(b1));
}

__device__ __forceinline__ void cp16(uint32_t smem_addr, const void* gptr) {
    asm volatile("cp.async.cg.shared.global [%0], [%1], 16;\n"
                 :: "r"(smem_addr), "l"(gptr));
}
__device__ __forceinline__ void cp_commit() {
    asm volatile("cp.async.commit_group;\n");
}
template <int N>
__device__ __forceinline__ void cp_wait() {
    asm volatile("cp.async.wait_group %0;\n" :: "n"(N));
}

// ---------------------------------------------------------------------------
// Pre-pass 1: fp32 -> packed fp16 along rows (x): [m][k] -> [m][kpair]
// ---------------------------------------------------------------------------
__global__ void cvt_h_kernel(const float4* __restrict__ s,
                             uint2* __restrict__ d, int n4)
{
    int i = blockIdx.x * blockDim.x + threadIdx.x;
    if (i < n4) {
        float4 v = s[i];
        d[i] = make_uint2(pack2(v.x, v.y), pack2(v.z, v.w));
    }
}

// ---------------------------------------------------------------------------
// Pre-pass 2: weights [K][N] fp32 -> packed-transposed-pair [K/2][N] half2:
// wp[kp*N + n] = (w[2kp][n], w[2kp+1][n])
// ---------------------------------------------------------------------------
__global__ void pack_wT_kernel(const float* __restrict__ w,
                               uint32_t* __restrict__ wp, int N, int K)
{
    int i = blockIdx.x * blockDim.x + threadIdx.x;
    if (i < (K / 2) * N) {
        int kp = i / N, n = i - kp * N;
        wp[i] = pack2(w[(2 * kp) * N + n], w[(2 * kp + 1) * N + n]);
    }
}

// ---------------------------------------------------------------------------
// fp16 tensor-core GEMM, cp.async 3-stage pipeline, BK=32 elements.
// C[M,N] = A[M,K] @ B[K,N] + bias.  CTA 128x128, 256 thr, 8 warps (4Mx2N),
// warp tile 32x64, mma m16n8k16.
// A packed [m][kpair]; B packed-T [kpair][n].
// EPI=0: scatter fp16 to g_Qh/g_Kh (packed) and g_Vth (transposed), Q*0.125.
// EPI=1: fp32 dense write to Cout.
// ---------------------------------------------------------------------------
#define ASTR 20    // A smem words/row (16 used + 4 pad): a-frag banks (20g+t)%32 unique
#define BSTR 136   // B smem words/row (128 + 8 pad): b-frag banks (8t+g)%32 unique
#define STAGES 3
#define GEMM_SMEM ((STAGES * 128 * ASTR + STAGES * 16 * BSTR) * 4)

template <int EPI>
__global__ __launch_bounds__(256, 2)
void mma_gemm_kernel(const uint32_t* __restrict__ A,
                     const uint32_t* __restrict__ Bm,
                     const float* __restrict__ bias, float* __restrict__ Cout,
                     int N, int K)
{
    extern __shared__ uint32_t gsm[];
    uint32_t* As = gsm;                          // STAGES * 128 * ASTR
    uint32_t* Bs = gsm + STAGES * 128 * ASTR;    // STAGES * 16 * BSTR

    const int tid   = threadIdx.x;
    const int lane  = tid & 31;
    const int warp  = tid >> 5;
    const int warpM = warp & 3;
    const int warpN = warp >> 2;
    const int g     = lane >> 2;
    const int t     = lane & 3;

    const int bm = blockIdx.y * 128;
    const int bn = blockIdx.x * 128;

    const int Kw = K >> 1;                       // words per A row

    // loader coords: A tile 128 rows x 16 words; B tile 16 rows x 128 words
    const int arow  = tid >> 1;                  // 0..127
    const int acolw = (tid & 1) << 3;            // 0 or 8
    const int brow  = tid >> 4;                  // 0..15
    const int bcolw = (tid & 15) << 3;           // 0..120

    const int iters = K >> 5;                    // K/32

    auto issue = [&](int st, int it) {
        uint32_t* as = As + st * 128 * ASTR;
        uint32_t* bs = Bs + st * 16 * BSTR;
        const int k0w = it * 16;                 // word offset in K
        cp16((uint32_t)__cvta_generic_to_shared(&as[arow * ASTR + acolw]),
             &A[(bm + arow) * Kw + k0w + acolw]);
        cp16((uint32_t)__cvta_generic_to_shared(&as[arow * ASTR + acolw + 4]),
             &A[(bm + arow) * Kw + k0w + acolw + 4]);
        cp16((uint32_t)__cvta_generic_to_shared(&bs[brow * BSTR + bcolw]),
             &Bm[(k0w + brow) * N + bn + bcolw]);
        cp16((uint32_t)__cvta_generic_to_shared(&bs[brow * BSTR + bcolw + 4]),
             &Bm[(k0w + brow) * N + bn + bcolw + 4]);
    };

    float acc[2][8][4] = {};

    issue(0, 0); cp_commit();
    issue(1, 1); cp_commit();

    for (int it = 0; it < iters; it++) {
        cp_wait<1>();
        __syncthreads();

        if (it + 2 < iters) issue((it + 2) % STAGES, it + 2);
        cp_commit();

        const uint32_t* as = As + (it % STAGES) * 128 * ASTR;
        const uint32_t* bs = Bs + (it % STAGES) * 16 * BSTR;

        #pragma unroll
        for (int ks = 0; ks < 2; ks++) {         // two k16 steps (BK=32)
            const int kow = ks * 8;
            uint32_t af[2][4];
            uint32_t bf[8][2];
            #pragma unroll
            for (int mt = 0; mt < 2; mt++) {
                const int mb = warpM * 32 + mt * 16;
                af[mt][0] = as[(mb + g)     * ASTR + kow + t];
                af[mt][1] = as[(mb + g + 8) * ASTR + kow + t];
                af[mt][2] = as[(mb + g)     * ASTR + kow + t + 4];
                af[mt][3] = as[(mb + g + 8) * ASTR + kow + t + 4];
            }
            #pragma unroll
            for (int nt = 0; nt < 8; nt++) {
                const int nb = warpN * 64 + nt * 8;
                bf[nt][0] = bs[(kow + t)     * BSTR + nb + g];
                bf[nt][1] = bs[(kow + t + 4) * BSTR + nb + g];
            }
            #pragma unroll
            for (int mt = 0; mt < 2; mt++)
                #pragma unroll
                for (int nt = 0; nt < 8; nt++)
                    mma_f16(acc[mt][nt], af[mt], bf[nt][0], bf[nt][1]);
        }
        __syncthreads();
    }

    // ---- epilogue ----
    #pragma unroll
    for (int mt = 0; mt < 2; mt++) {
        #pragma unroll
        for (int nt = 0; nt < 8; nt++) {
            const int row0 = bm + warpM * 32 + mt * 16 + g;
            const int col  = bn + warpN * 64 + nt * 8 + 2 * t;
            const float b0 = bias[col];
            const float b1 = bias[col + 1];
            float2 v0 = make_float2(acc[mt][nt][0] + b0, acc[mt][nt][1] + b1);
            float2 v1 = make_float2(acc[mt][nt][2] + b0, acc[mt][nt][3] + b1);
            if (EPI == 1) {
                *(float2*)&Cout[row0 * N + col]       = v0;
                *(float2*)&Cout[(row0 + 8) * N + col] = v1;
            } else {
                const int which = col >> 10;          // 0=q,1=k,2=v
                const int h     = (col >> 6) & 15;
                const int d     = col & 63;
                const int r1    = row0 + 8;
                const int b0i = row0 >> 11, t0i = row0 & 2047;
                const int b1i = r1   >> 11, t1i = r1   & 2047;
                const int bh0 = (b0i << 4) + h;
                const int bh1 = (b1i << 4) + h;
                if (which == 0) {
                    g_Qh[(bh0 * TT + t0i) * 32 + (d >> 1)] =
                        pack2(v0.x * 0.125f, v0.y * 0.125f);
                    g_Qh[(bh1 * TT + t1i) * 32 + (d >> 1)] =
                        pack2(v1.x * 0.125f, v1.y * 0.125f);
                } else if (which == 1) {
                    g_Kh[(bh0 * TT + t0i) * 32 + (d >> 1)] = pack2(v0.x, v0.y);
                    g_Kh[(bh1 * TT + t1i) * 32 + (d >> 1)] = pack2(v1.x, v1.y);
                } else {
                    // V transposed: [B,H,HD,T]
                    g_Vth[(bh0 * HD + d)     * TT + t0i] = __float2half_rn(v0.x);
                    g_Vth[(bh0 * HD + d + 1) * TT + t0i] = __float2half_rn(v0.y);
                    g_Vth[(bh1 * HD + d)     * TT + t1i] = __float2half_rn(v1.x);
                    g_Vth[(bh1 * HD + d + 1) * TT + t1i] = __float2half_rn(v1.y);
                }
            }
        }
    }
}

// ---------------------------------------------------------------------------
// Causal flash attention, fp16 mma m16n8k16, 2-stage cp.async K/V pipeline.
// Grid (T/64, B*H), 128 threads = 4 warps; warp w owns rows qblk*64+16w..+15.
// Q pre-scaled; K packed [token][dpair]; V transposed [d][token].
// Output fp16 packed g_Yh [B,T,Dpair].
// ---------------------------------------------------------------------------
#define KSTR2 36   // words/row (32 + 4 pad): frag banks (4g+t)%32 unique
#define VSTR2 36
#define PSTR2 36
#define ATTN_SMEM_BYTES ((2 * 64 * KSTR2 + 2 * 64 * VSTR2 + 4 * 16 * PSTR2) * 4)

__global__ __launch_bounds__(128)
void attn_mma_kernel()
{
    extern __shared__ uint32_t dyn[];
    uint32_t* KsB = dyn;                          // 2 * 64*KSTR2
    uint32_t* VsB = KsB + 2 * 64 * KSTR2;         // 2 * 64*VSTR2
    uint32_t* Ps  = VsB + 2 * 64 * VSTR2;         // 4 * 16*PSTR2

    const int bh   = blockIdx.y;
    const int b    = bh >> 4;
    const int h    = bh & 15;
    const int qblk = blockIdx.x;
    const int tid  = threadIdx.x;
    const int lane = tid & 31;
    const int warp = tid >> 5;
    const int g    = lane >> 2;
    const int t    = lane & 3;
    uint32_t* Pw   = Ps + warp * 16 * PSTR2;

    // K tile: 64 rows(token) x 32 words; V^T tile: 64 rows(d) x 32 words(keypair)
    auto issue_kv = [&](int st, int jb) {
        const uint32_t* ktw = g_Kh + (bh * TT + jb * 64) * 32;
        const uint32_t* vtw = (const uint32_t*)g_Vth + (bh * HD) * (TT / 2) + jb * 32;
        uint32_t* ks = KsB + st * 64 * KSTR2;
        uint32_t* vs = VsB + st * 64 * VSTR2;
        #pragma unroll
        for (int l = 0; l < 4; l++) {
            const int idx  = tid + l * 128;       // 0..511
            const int row  = idx >> 3;            // 0..63
            const int colw = (idx & 7) << 2;      // 0..28
            cp16((uint32_t)__cvta_generic_to_shared(&ks[row * KSTR2 + colw]),
                 &ktw[row * 32 + colw]);
            cp16((uint32_t)__cvta_generic_to_shared(&vs[row * VSTR2 + colw]),
                 &vtw[row * (TT / 2) + colw]);
        }
    };

    // ---- stage this warp's Q rows through Pw, pull A-fragments ----
    uint32_t qf[4][4];
    {
        const uint32_t* qtw = g_Qh + (bh * TT + qblk * 64 + warp * 16) * 32;
        #pragma unroll
        for (int l = 0; l < 4; l++) {
            const int idx  = lane + l * 32;       // 0..127
            const int row  = idx >> 3;            // 0..15
            const int colw = (idx & 7) << 2;
            *(uint4*)&Pw[row * PSTR2 + colw] = *(const uint4*)&qtw[row * 32 + colw];
        }
        __syncwarp();
        #pragma unroll
        for (int c = 0; c < 4; c++) {             // 4 k16 chunks over HD=64
            qf[c][0] = Pw[g       * PSTR2 + c * 8 + t];
            qf[c][1] = Pw[(g + 8) * PSTR2 + c * 8 + t];
            qf[c][2] = Pw[g       * PSTR2 + c * 8 + t + 4];
            qf[c][3] = Pw[(g + 8) * PSTR2 + c * 8 + t + 4];
        }
        __syncwarp();
    }

    float o[8][4] = {};
    float mi0 = -1e30f, mi1 = -1e30f, li0 = 0.f, li1 = 0.f;
    const int row0 = qblk * 64 + warp * 16 + g;
    const int row1 = row0 + 8;

    issue_kv(0, 0);
    cp_commit();

    #pragma unroll 1
    for (int jb = 0; jb <= qblk; jb++) {
        if (jb + 1 <= qblk) issue_kv((jb + 1) & 1, jb + 1);
        cp_commit();
        cp_wait<1>();
        __syncthreads();

        const uint32_t* Ks = KsB + (jb & 1) * 64 * KSTR2;
        const uint32_t* Vs = VsB + (jb & 1) * 64 * VSTR2;

        // ---- S = Q @ K^T (Q pre-scaled) ----
        float s[8][4] = {};
        #pragma unroll
        for (int c = 0; c < 4; c++) {
            #pragma unroll
            for (int nf = 0; nf < 8; nf++) {
                const uint32_t b0 = Ks[(nf * 8 + g) * KSTR2 + c * 8 + t];
                const uint32_t b1 = Ks[(nf * 8 + g) * KSTR2 + c * 8 + t + 4];
                mma_f16(s[nf], qf[c], b0, b1);
            }
        }

        // ---- causal mask (diagonal tile only) ----
        if (jb == qblk) {
            #pragma unroll
            for (int nf = 0; nf < 8; nf++) {
                const int c0 = jb * 64 + nf * 8 + 2 * t;
                if (c0     > row0) s[nf][0] = -1e30f;
                if (c0 + 1 > row0) s[nf][1] = -1e30f;
                if (c0     > row1) s[nf][2] = -1e30f;
                if (c0 + 1 > row1) s[nf][3] = -1e30f;
            }
        }

        // ---- online softmax (fp32) ----
        float lm0 = -1e30f, lm1 = -1e30f;
        #pragma unroll
        for (int nf = 0; nf < 8; nf++) {
            lm0 = fmaxf(lm0, fmaxf(s[nf][0], s[nf][1]));
            lm1 = fmaxf(lm1, fmaxf(s[nf][2], s[nf][3]));
        }
        lm0 = fmaxf(lm0, __shfl_xor_sync(0xffffffffu, lm0, 1));
        lm0 = fmaxf(lm0, __shfl_xor_sync(0xffffffffu, lm0, 2));
        lm1 = fmaxf(lm1, __shfl_xor_sync(0xffffffffu, lm1, 1));
        lm1 = fmaxf(lm1, __shfl_xor_sync(0xffffffffu, lm1, 2));
        const float mn0 = fmaxf(mi0, lm0);
        const float mn1 = fmaxf(mi1, lm1);
        const float a0 = __expf(mi0 - mn0);
        const float a1 = __expf(mi1 - mn1);
        float ls0 = 0.f, ls1 = 0.f;
        #pragma unroll
        for (int nf = 0; nf < 8; nf++) {
            s[nf][0] = __expf(s[nf][0] - mn0); ls0 += s[nf][0];
            s[nf][1] = __expf(s[nf][1] - mn0); ls0 += s[nf][1];
            s[nf][2] = __expf(s[nf][2] - mn1); ls1 += s[nf][2];
            s[nf][3] = __expf(s[nf][3] - mn1); ls1 += s[nf][3];
        }
        ls0 += __shfl_xor_sync(0xffffffffu, ls0, 1);
        ls0 += __shfl_xor_sync(0xffffffffu, ls0, 2);
        ls1 += __shfl_xor_sync(0xffffffffu, ls1, 1);
        ls1 += __shfl_xor_sync(0xffffffffu, ls1, 2);
        li0 = li0 * a0 + ls0;  mi0 = mn0;
        li1 = li1 * a1 + ls1;  mi1 = mn1;
        #pragma unroll
        for (int nf = 0; nf < 8; nf++) {
            o[nf][0] *= a0; o[nf][1] *= a0;
            o[nf][2] *= a1; o[nf][3] *= a1;
        }

        // ---- P -> per-warp smem as half2 [row][keypair] ----
        #pragma unroll
        for (int nf = 0; nf < 8; nf++) {
            Pw[g       * PSTR2 + nf * 4 + t] = pack2(s[nf][0], s[nf][1]);
            Pw[(g + 8) * PSTR2 + nf * 4 + t] = pack2(s[nf][2], s[nf][3]);
        }
        __syncwarp();

        // ---- O += P @ V  (V^T tile: rows=d, cols=keypair) ----
        #pragma unroll
        for (int kc = 0; kc < 4; kc++) {          // 4 k16 chunks over 64 keys
            uint32_t af[4];
            af[0] = Pw[g       * PSTR2 + kc * 8 + t];
            af[1] = Pw[(g + 8) * PSTR2 + kc * 8 + t];
            af[2] = Pw[g       * PSTR2 + kc * 8 + t + 4];
            af[3] = Pw[(g + 8) * PSTR2 + kc * 8 + t + 4];
            #pragma unroll
            for (int nf = 0; nf < 8; nf++) {      // d frags
                const uint32_t b0 = Vs[(nf * 8 + g) * VSTR2 + kc * 8 + t];
                const uint32_t b1 = Vs[(nf * 8 + g) * VSTR2 + kc * 8 + t + 4];
                mma_f16(o[nf], af, b0, b1);
            }
        }
        __syncthreads();   // all warps done with this K/V stage before reuse
    }

    // ---- normalize + write fp16 packed [B,T,Dpair] ----
    const float inv0 = 1.f / li0;
    const float inv1 = 1.f / li1;
    uint32_t* y0 = g_Yh + (b * TT + row0) * (DD / 2) + h * 32;
    uint32_t* y1 = g_Yh + (b * TT + row1) * (DD / 2) + h * 32;
    #pragma unroll
    for (int nf = 0; nf < 8; nf++) {
        y0[nf * 4 + t] = pack2(o[nf][0] * inv0, o[nf][1] * inv0);
        y1[nf * 4 + t] = pack2(o[nf][2] * inv1, o[nf][3] * inv1);
    }
}

// ---------------------------------------------------------------------------
// Launch. Inputs: x, causal_mask(unused), w_qkv, b_qkv, w_out, b_out.
// ---------------------------------------------------------------------------
extern "C" void kernel_launch(void* const* d_in, const int* in_sizes, int n_in,
                              void* d_out, int out_size)
{
    const float* x     = (const float*)d_in[0];
    const float* w_qkv = (const float*)d_in[2];
    const float* b_qkv = (const float*)d_in[3];
    const float* w_out = (const float*)d_in[4];
    const float* b_out = (const float*)d_in[5];
    float* out = (float*)d_out;

    uint32_t *xh, *wqkvh, *woh, *yh;
    cudaGetSymbolAddress((void**)&xh,    g_xh);
    cudaGetSymbolAddress((void**)&wqkvh, g_wqkvh);
    cudaGetSymbolAddress((void**)&woh,   g_woh);
    cudaGetSymbolAddress((void**)&yh,    g_Yh);

    cudaFuncSetAttribute(mma_gemm_kernel<0>,
                         cudaFuncAttributeMaxDynamicSharedMemorySize, GEMM_SMEM);
    cudaFuncSetAttribute(mma_gemm_kernel<1>,
                         cudaFuncAttributeMaxDynamicSharedMemorySize, GEMM_SMEM);
    cudaFuncSetAttribute(attn_mma_kernel,
                         cudaFuncAttributeMaxDynamicSharedMemorySize,
                         ATTN_SMEM_BYTES);

    // pre-convert: x -> packed fp16 rows; weights -> packed-T fp16
    cvt_h_kernel<<<(BT * DD / 4 + 255) / 256, 256>>>(
        (const float4*)x, (uint2*)xh, BT * DD / 4);
    pack_wT_kernel<<<((DD / 2) * 3 * DD + 255) / 256, 256>>>(
        w_qkv, wqkvh, 3 * DD, DD);
    pack_wT_kernel<<<((DD / 2) * DD + 255) / 256, 256>>>(
        w_out, woh, DD, DD);

    mma_gemm_kernel<0><<<dim3((3 * DD) / 128, BT / 128), 256, GEMM_SMEM>>>(
        xh, wqkvh, b_qkv, nullptr, 3 * DD, DD);
    attn_mma_kernel<<<dim3(TT / 64, BB * HH), 128, ATTN_SMEM_BYTES>>>();
    mma_gemm_kernel<1><<<dim3(DD / 128, BT / 128), 256, GEMM_SMEM>>>(
        yh, woh, b_out, out, DD, DD);
}